// round 1
// baseline (speedup 1.0000x reference)
#include <cuda_runtime.h>
#include <math.h>

#define NN 50000
#define DD 128
#define TT 4
#define EE 150000
#define ND (NN*DD)

// Scratch layout (floats):
// H[ND], AGG[ND], XW[ND], TMP[ND], Q[ND], K[ND], V[ND], KA[4*ND], VM[4*ND],
// AL[N*8], AR[N*8], M[N*8], S[N*8], P[(E+N)*8], ATT[4*E*8]
__device__ float d_scratch[104000000];

__device__ __forceinline__ float gelu_f(float x) {
    return 0.5f * x * (1.0f + erff(x * 0.7071067811865476f));
}

__device__ __forceinline__ void atomicMaxFloat(float* addr, float val) {
    if (val >= 0.0f) atomicMax((int*)addr, __float_as_int(val));
    else             atomicMin((unsigned int*)addr, __float_as_uint(val));
}

__device__ __forceinline__ float blockSum128(float v) {
    v += __shfl_xor_sync(0xffffffffu, v, 16);
    v += __shfl_xor_sync(0xffffffffu, v, 8);
    v += __shfl_xor_sync(0xffffffffu, v, 4);
    v += __shfl_xor_sync(0xffffffffu, v, 2);
    v += __shfl_xor_sync(0xffffffffu, v, 1);
    __shared__ float ws[4];
    if ((threadIdx.x & 31) == 0) ws[threadIdx.x >> 5] = v;
    __syncthreads();
    return ws[0] + ws[1] + ws[2] + ws[3];
}

// ---------------- elementwise ----------------
__global__ void add3_k(const float* __restrict__ a, const float* __restrict__ b,
                       const float* __restrict__ c, float* __restrict__ o) {
    int i = blockIdx.x * blockDim.x + threadIdx.x;
    if (i < ND) o[i] = a[i] + b[i] + c[i];
}

__global__ void fill_k(float* __restrict__ p, int n, float v) {
    int i = blockIdx.x * blockDim.x + threadIdx.x;
    if (i < n) p[i] = v;
}

__global__ void gelu_k(const float* __restrict__ in, float* __restrict__ out) {
    int i = blockIdx.x * blockDim.x + threadIdx.x;
    if (i < ND) out[i] = gelu_f(in[i]);
}

// ---------------- GEMM: C[M,128] = A[M,128] @ B[128,128] (+bias) ----------------
__global__ __launch_bounds__(256) void gemm128(
    const float* __restrict__ A, const float* __restrict__ B,
    const float* __restrict__ bias, float* __restrict__ C, int Mrows)
{
    __shared__ float As[8][132];   // [k][row], padded, 16B-aligned rows
    __shared__ float Bs[8][128];   // [k][col]
    const int tid = threadIdx.x;
    const int tx = tid & 15;        // col group
    const int ty = tid >> 4;        // row group
    const int rbase = blockIdx.x * 128;

    float acc[8][8];
#pragma unroll
    for (int i = 0; i < 8; i++)
#pragma unroll
        for (int j = 0; j < 8; j++) acc[i][j] = 0.0f;

    const int arow = tid >> 1;          // 0..127
    const int aq   = (tid & 1) * 4;     // 0 or 4
    const int bk   = tid >> 5;          // 0..7
    const int bc   = (tid & 31) * 4;

    for (int k0 = 0; k0 < 128; k0 += 8) {
        float4 av = make_float4(0.f, 0.f, 0.f, 0.f);
        int r = rbase + arow;
        if (r < Mrows) av = *(const float4*)&A[r * 128 + k0 + aq];
        As[aq + 0][arow] = av.x;
        As[aq + 1][arow] = av.y;
        As[aq + 2][arow] = av.z;
        As[aq + 3][arow] = av.w;
        *(float4*)&Bs[bk][bc] = *(const float4*)&B[(k0 + bk) * 128 + bc];
        __syncthreads();
#pragma unroll
        for (int k = 0; k < 8; k++) {
            float a[8], b[8];
            *(float4*)&a[0] = *(const float4*)&As[k][ty * 8];
            *(float4*)&a[4] = *(const float4*)&As[k][ty * 8 + 4];
            *(float4*)&b[0] = *(const float4*)&Bs[k][tx * 8];
            *(float4*)&b[4] = *(const float4*)&Bs[k][tx * 8 + 4];
#pragma unroll
            for (int i = 0; i < 8; i++)
#pragma unroll
                for (int j = 0; j < 8; j++) acc[i][j] += a[i] * b[j];
        }
        __syncthreads();
    }

    float bb[8];
#pragma unroll
    for (int j = 0; j < 8; j++) bb[j] = bias ? bias[tx * 8 + j] : 0.0f;

#pragma unroll
    for (int i = 0; i < 8; i++) {
        int r = rbase + ty * 8 + i;
        if (r < Mrows) {
#pragma unroll
            for (int j = 0; j < 8; j++)
                C[r * 128 + tx * 8 + j] = acc[i][j] + bb[j];
        }
    }
}

// ---------------- GAT ----------------
// AL[i,h] = sum_d XW[i,h*16+d]*asrc[h*16+d];  AR likewise with adst
__global__ void gat_alr(const float* __restrict__ XW,
                        const float* __restrict__ asrc, const float* __restrict__ adst,
                        float* __restrict__ AL, float* __restrict__ AR)
{
    int g = blockIdx.x * blockDim.x + threadIdx.x;
    if (g >= NN * 8) return;
    int i = g >> 3, h = g & 7;
    const float* xp = XW + i * DD + h * 16;
    const float* ap = asrc + h * 16;
    const float* bp = adst + h * 16;
    float s1 = 0.f, s2 = 0.f;
#pragma unroll
    for (int d = 0; d < 16; d++) { float x = xp[d]; s1 += x * ap[d]; s2 += x * bp[d]; }
    AL[g] = s1; AR[g] = s2;
}

__global__ void gat_edge_max(const int* __restrict__ ei,
                             const float* __restrict__ AL, const float* __restrict__ AR,
                             float* __restrict__ M)
{
    int g = blockIdx.x * blockDim.x + threadIdx.x;
    if (g >= (EE + NN) * 8) return;
    int e = g >> 3, h = g & 7;
    int src, dst;
    if (e < EE) { src = ei[e]; dst = ei[EE + e]; } else { src = dst = e - EE; }
    float v = AL[src * 8 + h] + AR[dst * 8 + h];
    v = v > 0.f ? v : 0.2f * v;
    atomicMaxFloat(M + dst * 8 + h, v);
}

__global__ void gat_edge_exp(const int* __restrict__ ei,
                             const float* __restrict__ AL, const float* __restrict__ AR,
                             const float* __restrict__ M, float* __restrict__ S,
                             float* __restrict__ P)
{
    int g = blockIdx.x * blockDim.x + threadIdx.x;
    if (g >= (EE + NN) * 8) return;
    int e = g >> 3, h = g & 7;
    int src, dst;
    if (e < EE) { src = ei[e]; dst = ei[EE + e]; } else { src = dst = e - EE; }
    float v = AL[src * 8 + h] + AR[dst * 8 + h];
    v = v > 0.f ? v : 0.2f * v;
    float p = expf(v - M[dst * 8 + h]);
    P[g] = p;
    atomicAdd(S + dst * 8 + h, p);
}

// warp-per-edge scatter: AGG[dst,:] += VAL[src,:] * (P[e,h]/S[dst,h])
__global__ void scatter_k(const int* __restrict__ ei, int nself,
                          const float* __restrict__ VAL, const float* __restrict__ P,
                          const float* __restrict__ S, float* __restrict__ AGG)
{
    int g = blockIdx.x * blockDim.x + threadIdx.x;
    int e = g >> 5, lane = g & 31;
    int tot = EE + nself;
    if (e >= tot) return;
    int src, dst;
    if (e < EE) { src = ei[e]; dst = ei[EE + e]; } else { src = dst = e - EE; }
    int h = lane >> 2;
    float alpha = P[e * 8 + h] / S[dst * 8 + h];
    int c = lane << 2;
    float4 xv = *(const float4*)&VAL[src * DD + c];
    float* ap = AGG + dst * DD + c;
    atomicAdd(ap + 0, xv.x * alpha);
    atomicAdd(ap + 1, xv.y * alpha);
    atomicAdd(ap + 2, xv.z * alpha);
    atomicAdd(ap + 3, xv.w * alpha);
}

// H = gelu(H + rmsnorm(AGG + sum_t b[t], g)), in place
__global__ void finalize_gat(float* __restrict__ H, const float* __restrict__ AGG,
                             const float* __restrict__ b, const float* __restrict__ g)
{
    int i = blockIdx.x, t = threadIdx.x;
    float v = AGG[i * DD + t] + b[t] + b[DD + t] + b[2 * DD + t] + b[3 * DD + t];
    float ss = blockSum128(v * v);
    float r = g[t] * v * rsqrtf(ss * (1.0f / DD) + 1e-6f);
    float x = H[i * DD + t] + r;
    H[i * DD + t] = gelu_f(x);
}

// ---------------- HGT ----------------
// Y[n, h*16+f] = sum_d X[n, h*16+d] * R[h,d,f]   (R: 8x16x16 for one type)
__global__ void hgt_rel(const float* __restrict__ X, const float* __restrict__ R,
                        float* __restrict__ Y)
{
    int g = blockIdx.x * blockDim.x + threadIdx.x;
    if (g >= ND) return;
    int n = g >> 7, c = g & 127;
    int h = c >> 4, f = c & 15;
    const float* xp = X + n * DD + h * 16;
    const float* rp = R + h * 256 + f;
    float acc = 0.f;
#pragma unroll
    for (int d = 0; d < 16; d++) acc += xp[d] * rp[d * 16];
    Y[g] = acc;
}

__global__ void hgt_att(const int* __restrict__ ei, const float* __restrict__ Q,
                        const float* __restrict__ KA, const float* __restrict__ prel_t,
                        float* __restrict__ ATTt, float* __restrict__ M)
{
    int g = blockIdx.x * blockDim.x + threadIdx.x;
    if (g >= EE * 8) return;
    int e = g >> 3, h = g & 7;
    int src = ei[e], dst = ei[EE + e];
    const float* qp = Q + dst * DD + h * 16;
    const float* kp = KA + src * DD + h * 16;
    float acc = 0.f;
#pragma unroll
    for (int f = 0; f < 16; f++) acc += qp[f] * kp[f];
    acc *= prel_t[h] * 0.25f;   // / sqrt(16)
    ATTt[g] = acc;
    atomicMaxFloat(M + dst * 8 + h, acc);
}

__global__ void hgt_exp(const int* __restrict__ ei, float* __restrict__ ATTt,
                        const float* __restrict__ M, float* __restrict__ S)
{
    int g = blockIdx.x * blockDim.x + threadIdx.x;
    if (g >= EE * 8) return;
    int e = g >> 3, h = g & 7;
    int dst = ei[EE + e];
    float p = expf(ATTt[g] - M[dst * 8 + h]);
    ATTt[g] = p;
    atomicAdd(S + dst * 8 + h, p);
}

// out = gelu(H + rmsnorm(beta*OUT2 + (1-beta)*H, g3))
__global__ void finalize_hgt(const float* __restrict__ H, const float* __restrict__ OUT2,
                             const float* __restrict__ skip, const float* __restrict__ g3,
                             float* __restrict__ out)
{
    int i = blockIdx.x, t = threadIdx.x;
    float beta = 1.0f / (1.0f + expf(-skip[0]));
    float hv = H[i * DD + t];
    float y = beta * OUT2[i * DD + t] + (1.0f - beta) * hv;
    float ss = blockSum128(y * y);
    float r = g3[t] * y * rsqrtf(ss * (1.0f / DD) + 1e-6f);
    out[i * DD + t] = gelu_f(hv + r);
}

// ---------------- driver ----------------
extern "C" void kernel_launch(void* const* d_in, const int* in_sizes, int n_in,
                              void* d_out, int out_size)
{
    const float* zL  = (const float*)d_in[0];
    const float* zH  = (const float*)d_in[1];
    const float* xe  = (const float*)d_in[2];
    const float* W1  = (const float*)d_in[3];
    const float* as1 = (const float*)d_in[4];
    const float* ad1 = (const float*)d_in[5];
    const float* b1  = (const float*)d_in[6];
    const float* W2  = (const float*)d_in[7];
    const float* as2 = (const float*)d_in[8];
    const float* ad2 = (const float*)d_in[9];
    const float* b2  = (const float*)d_in[10];
    const float* Wk  = (const float*)d_in[11];
    const float* bk  = (const float*)d_in[12];
    const float* Wq  = (const float*)d_in[13];
    const float* bq  = (const float*)d_in[14];
    const float* Wv  = (const float*)d_in[15];
    const float* bv  = (const float*)d_in[16];
    const float* arel= (const float*)d_in[17];
    const float* mrel= (const float*)d_in[18];
    const float* prel= (const float*)d_in[19];
    const float* Wo  = (const float*)d_in[20];
    const float* bo  = (const float*)d_in[21];
    const float* skip= (const float*)d_in[22];
    const float* g1  = (const float*)d_in[23];
    const float* g2  = (const float*)d_in[24];
    const float* g3  = (const float*)d_in[25];
    const int* ei[4] = {(const int*)d_in[26], (const int*)d_in[27],
                        (const int*)d_in[28], (const int*)d_in[29]};

    float* SB = nullptr;
    cudaGetSymbolAddress((void**)&SB, d_scratch);
    float* H   = SB;
    float* AGG = SB + (size_t)ND;
    float* XW  = SB + 2 * (size_t)ND;
    float* TMP = SB + 3 * (size_t)ND;
    float* Q   = SB + 4 * (size_t)ND;
    float* K   = SB + 5 * (size_t)ND;
    float* V   = SB + 6 * (size_t)ND;
    float* KA  = SB + 7 * (size_t)ND;   // 4*ND
    float* VM  = SB + 11 * (size_t)ND;  // 4*ND
    float* AL  = SB + 15 * (size_t)ND;
    float* AR  = AL + NN * 8;
    float* Mx  = AR + NN * 8;
    float* Sx  = Mx + NN * 8;
    float* P   = Sx + NN * 8;                 // (E+N)*8
    float* ATT = P + (size_t)(EE + NN) * 8;   // 4*E*8

    const int TPB = 256;
    const int gND = (ND + TPB - 1) / TPB;
    const int gN8 = (NN * 8 + TPB - 1) / TPB;
    const int gE8 = ((EE + NN) * 8 + TPB - 1) / TPB;
    const int gGEMM = (NN + 127) / 128;

    add3_k<<<gND, TPB>>>(zL, zH, xe, H);

    const float* Ws[2]  = {W1, W2};
    const float* ass[2] = {as1, as2};
    const float* ads[2] = {ad1, ad2};
    const float* bs[2]  = {b1, b2};
    const float* gs[2]  = {g1, g2};

    for (int L = 0; L < 2; L++) {
        cudaMemsetAsync(AGG, 0, (size_t)ND * sizeof(float));
        for (int t = 0; t < TT; t++) {
            gemm128<<<gGEMM, 256>>>(H, Ws[L] + (size_t)t * DD * DD, nullptr, XW, NN);
            gat_alr<<<gN8, TPB>>>(XW, ass[L] + t * DD, ads[L] + t * DD, AL, AR);
            fill_k<<<gN8, TPB>>>(Mx, NN * 8, -INFINITY);
            cudaMemsetAsync(Sx, 0, (size_t)NN * 8 * sizeof(float));
            gat_edge_max<<<gE8, TPB>>>(ei[t], AL, AR, Mx);
            gat_edge_exp<<<gE8, TPB>>>(ei[t], AL, AR, Mx, Sx, P);
            scatter_k<<<((EE + NN) * 32 + TPB - 1) / TPB, TPB>>>(ei[t], NN, XW, P, Sx, AGG);
        }
        finalize_gat<<<NN, 128>>>(H, AGG, bs[L], gs[L]);
    }

    // HGT
    gemm128<<<gGEMM, 256>>>(H, Wk, bk, K, NN);
    gemm128<<<gGEMM, 256>>>(H, Wq, bq, Q, NN);
    gemm128<<<gGEMM, 256>>>(H, Wv, bv, V, NN);
    for (int t = 0; t < TT; t++) {
        hgt_rel<<<gND, TPB>>>(K, arel + t * 2048, KA + (size_t)t * ND);
        hgt_rel<<<gND, TPB>>>(V, mrel + t * 2048, VM + (size_t)t * ND);
    }
    fill_k<<<gN8, TPB>>>(Mx, NN * 8, -INFINITY);
    cudaMemsetAsync(Sx, 0, (size_t)NN * 8 * sizeof(float));
    cudaMemsetAsync(AGG, 0, (size_t)ND * sizeof(float));
    const int gEH = (EE * 8 + TPB - 1) / TPB;
    for (int t = 0; t < TT; t++)
        hgt_att<<<gEH, TPB>>>(ei[t], Q, KA + (size_t)t * ND, prel + t * 8,
                              ATT + (size_t)t * EE * 8, Mx);
    for (int t = 0; t < TT; t++)
        hgt_exp<<<gEH, TPB>>>(ei[t], ATT + (size_t)t * EE * 8, Mx, Sx);
    for (int t = 0; t < TT; t++)
        scatter_k<<<(EE * 32 + TPB - 1) / TPB, TPB>>>(ei[t], 0, VM + (size_t)t * ND,
                                                      ATT + (size_t)t * EE * 8, Sx, AGG);
    gelu_k<<<gND, TPB>>>(AGG, TMP);
    gemm128<<<gGEMM, 256>>>(TMP, Wo, bo, XW, NN);
    finalize_hgt<<<NN, 128>>>(H, XW, skip, g3, (float*)d_out);
}

// round 3
// speedup vs baseline: 1.3944x; 1.3944x over previous
#include <cuda_runtime.h>
#include <math.h>

#define NN 50000
#define DD 128
#define TT 4
#define EE 150000
#define ND (NN*DD)

__device__ float d_scratch[104000000];

__device__ __forceinline__ float gelu_f(float x) {
    return 0.5f * x * (1.0f + erff(x * 0.7071067811865476f));
}

// ---------------- elementwise ----------------
__global__ void add3_k(const float* __restrict__ a, const float* __restrict__ b,
                       const float* __restrict__ c, float* __restrict__ o) {
    int i = blockIdx.x * blockDim.x + threadIdx.x;
    if (i < ND) o[i] = a[i] + b[i] + c[i];
}

// ---------------- CSR build ----------------
__global__ void deg_count(const int* __restrict__ e0, const int* __restrict__ e1,
                          const int* __restrict__ e2, const int* __restrict__ e3,
                          int* __restrict__ deg) {
    int g = blockIdx.x * blockDim.x + threadIdx.x;
    if (g >= 4 * EE) return;
    int t = g / EE, e = g - t * EE;
    const int* ei = t == 0 ? e0 : t == 1 ? e1 : t == 2 ? e2 : e3;
    atomicAdd(deg + t * NN + ei[EE + e], 1);
}

__global__ void scan_k(const int* __restrict__ deg, int* __restrict__ rowptr) {
    int t = blockIdx.x;
    const int* d = deg + t * NN;
    int* rp = rowptr + t * (NN + 1);
    __shared__ int warpsum[32];
    __shared__ int s_carry;
    if (threadIdx.x == 0) { rp[0] = 0; s_carry = 0; }
    __syncthreads();
    int lane = threadIdx.x & 31, wid = threadIdx.x >> 5;
    for (int base = 0; base < NN; base += 1024) {
        int i = base + (int)threadIdx.x;
        int v = (i < NN) ? d[i] : 0;
        int x = v;
#pragma unroll
        for (int o = 1; o < 32; o <<= 1) {
            int y = __shfl_up_sync(0xffffffffu, x, o);
            if (lane >= o) x += y;
        }
        if (lane == 31) warpsum[wid] = x;
        __syncthreads();
        if (wid == 0) {
            int w = warpsum[lane];
#pragma unroll
            for (int o = 1; o < 32; o <<= 1) {
                int y = __shfl_up_sync(0xffffffffu, w, o);
                if (lane >= o) w += y;
            }
            warpsum[lane] = w;
        }
        __syncthreads();
        int incl = x + (wid > 0 ? warpsum[wid - 1] : 0) + s_carry;
        if (i < NN) rp[i + 1] = incl;
        __syncthreads();
        if (threadIdx.x == 1023) s_carry = incl;
        __syncthreads();
    }
}

__global__ void wofs_init(const int* __restrict__ rowptr, int* __restrict__ wofs) {
    int g = blockIdx.x * blockDim.x + threadIdx.x;
    if (g >= 4 * NN) return;
    int t = g / NN, n = g - t * NN;
    wofs[g] = rowptr[t * (NN + 1) + n];
}

__global__ void csr_fill(const int* __restrict__ e0, const int* __restrict__ e1,
                         const int* __restrict__ e2, const int* __restrict__ e3,
                         int* __restrict__ wofs, int* __restrict__ csrc, int* __restrict__ ceid) {
    int g = blockIdx.x * blockDim.x + threadIdx.x;
    if (g >= 4 * EE) return;
    int t = g / EE, e = g - t * EE;
    const int* ei = t == 0 ? e0 : t == 1 ? e1 : t == 2 ? e2 : e3;
    int src = ei[e], dst = ei[EE + e];
    int pos = atomicAdd(wofs + t * NN + dst, 1);
    csrc[t * EE + pos] = src;
    ceid[t * EE + pos] = e;
}

// ---------------- GEMM: C[M,128] = A[M,128] @ B[128,128] (+bias), FFMA2 ----------------
__global__ __launch_bounds__(256) void gemm128(
    const float* __restrict__ A, const float* __restrict__ B,
    const float* __restrict__ bias, float* __restrict__ C, int Mrows)
{
    __shared__ float As[8][132];   // [k][row]
    __shared__ float Bs[8][128];   // [k][col]
    const int tid = threadIdx.x;
    const int tx = tid & 15;
    const int ty = tid >> 4;
    const int rbase = blockIdx.x * 128;

    unsigned long long acc[8][4];
#pragma unroll
    for (int i = 0; i < 8; i++)
#pragma unroll
        for (int j = 0; j < 4; j++) acc[i][j] = 0ull;   // (0.f, 0.f)

    const int arow = tid >> 1;
    const int aq   = (tid & 1) * 4;
    const int bk   = tid >> 5;
    const int bc   = (tid & 31) * 4;

    for (int k0 = 0; k0 < 128; k0 += 8) {
        float4 av = make_float4(0.f, 0.f, 0.f, 0.f);
        int r = rbase + arow;
        if (r < Mrows) av = *(const float4*)&A[(size_t)r * 128 + k0 + aq];
        As[aq + 0][arow] = av.x;
        As[aq + 1][arow] = av.y;
        As[aq + 2][arow] = av.z;
        As[aq + 3][arow] = av.w;
        *(float4*)&Bs[bk][bc] = *(const float4*)&B[(size_t)(k0 + bk) * 128 + bc];
        __syncthreads();
#pragma unroll
        for (int k = 0; k < 8; k++) {
            float a[8];
            *(float4*)&a[0] = *(const float4*)&As[k][ty * 8];
            *(float4*)&a[4] = *(const float4*)&As[k][ty * 8 + 4];
            unsigned long long bp[4];
            ulonglong2 b01 = *(const ulonglong2*)&Bs[k][tx * 8];
            ulonglong2 b23 = *(const ulonglong2*)&Bs[k][tx * 8 + 4];
            bp[0] = b01.x; bp[1] = b01.y; bp[2] = b23.x; bp[3] = b23.y;
#pragma unroll
            for (int i = 0; i < 8; i++) {
                unsigned long long ap;
                asm("mov.b64 %0, {%1, %1};" : "=l"(ap) : "f"(a[i]));
#pragma unroll
                for (int j = 0; j < 4; j++)
                    asm("fma.rn.f32x2 %0, %1, %2, %0;" : "+l"(acc[i][j]) : "l"(ap), "l"(bp[j]));
            }
        }
        __syncthreads();
    }

    float bb[8];
#pragma unroll
    for (int j = 0; j < 8; j++) bb[j] = bias ? bias[tx * 8 + j] : 0.0f;

#pragma unroll
    for (int i = 0; i < 8; i++) {
        int r = rbase + ty * 8 + i;
        if (r < Mrows) {
            float o[8];
#pragma unroll
            for (int j = 0; j < 4; j++) {
                float lo, hi;
                asm("mov.b64 {%0, %1}, %2;" : "=f"(lo), "=f"(hi) : "l"(acc[i][j]));
                o[2 * j] = lo + bb[2 * j];
                o[2 * j + 1] = hi + bb[2 * j + 1];
            }
            *(float4*)&C[(size_t)r * 128 + tx * 8]     = make_float4(o[0], o[1], o[2], o[3]);
            *(float4*)&C[(size_t)r * 128 + tx * 8 + 4] = make_float4(o[4], o[5], o[6], o[7]);
        }
    }
}

// ---------------- GAT ----------------
// AL[t][i*8+h] = sum_d XW4[t][i,h*16+d]*asrc[t][h*16+d]; AR likewise
__global__ void gat_alr4(const float* __restrict__ XW4,
                         const float* __restrict__ asrc, const float* __restrict__ adst,
                         float* __restrict__ AL, float* __restrict__ AR)
{
    int t = blockIdx.y;
    int g = blockIdx.x * blockDim.x + threadIdx.x;
    if (g >= NN * 8) return;
    int i = g >> 3, h = g & 7;
    const float* xp = XW4 + (size_t)t * ND + (size_t)i * DD + h * 16;
    const float* ap = asrc + t * DD + h * 16;
    const float* bp = adst + t * DD + h * 16;
    float s1 = 0.f, s2 = 0.f;
#pragma unroll
    for (int d = 0; d < 16; d++) { float x = xp[d]; s1 += x * ap[d]; s2 += x * bp[d]; }
    AL[t * NN * 8 + g] = s1;
    AR[t * NN * 8 + g] = s2;
}

// Fused per-dst GAT aggregation (all 4 types) + bias + rmsnorm + residual + gelu.
// One warp per node. Updates H in place.
__global__ __launch_bounds__(256) void gat_agg(
    const int* __restrict__ rowptr, const int* __restrict__ csrc,
    const float* __restrict__ AL, const float* __restrict__ AR,
    const float* __restrict__ XW4,
    const float* __restrict__ b, const float* __restrict__ g,
    float* __restrict__ H)
{
    int n = (blockIdx.x * blockDim.x + threadIdx.x) >> 5;
    if (n >= NN) return;
    int lane = threadIdx.x & 31;
    int hsrc = lane >> 2;        // head owning my 4 channels
    float4 acc = make_float4(0.f, 0.f, 0.f, 0.f);

    for (int t = 0; t < TT; t++) {
        const float* ALt = AL + (size_t)t * NN * 8;
        const float* ARt = AR + (size_t)t * NN * 8;
        const float* XWt = XW4 + (size_t)t * ND;
        int beg = rowptr[t * (NN + 1) + n];
        int end = rowptr[t * (NN + 1) + n + 1];

        float arh = 0.f, m = -1e30f, l_self = 0.f;
        if (lane < 8) {
            arh = ARt[n * 8 + lane];
            float v = ALt[n * 8 + lane] + arh;
            l_self = v > 0.f ? v : 0.2f * v;
            m = l_self;
        }
        for (int p = beg; p < end; p++) {
            int src = csrc[t * EE + p];
            if (lane < 8) {
                float v = ALt[src * 8 + lane] + arh;
                v = v > 0.f ? v : 0.2f * v;
                m = fmaxf(m, v);
            }
        }
        float s = 0.f;
        if (lane < 8) s = expf(l_self - m);
        for (int p = beg; p < end; p++) {
            int src = csrc[t * EE + p];
            if (lane < 8) {
                float v = ALt[src * 8 + lane] + arh;
                v = v > 0.f ? v : 0.2f * v;
                s += expf(v - m);
            }
        }
        float inv_s = (lane < 8) ? 1.0f / s : 0.f;
        // self-loop contribution
        {
            float p8 = (lane < 8) ? expf(l_self - m) * inv_s : 0.f;
            float a = __shfl_sync(0xffffffffu, p8, hsrc);
            float4 xv = *(const float4*)&XWt[(size_t)n * DD + lane * 4];
            acc.x += xv.x * a; acc.y += xv.y * a; acc.z += xv.z * a; acc.w += xv.w * a;
        }
        for (int p = beg; p < end; p++) {
            int src = csrc[t * EE + p];
            float p8 = 0.f;
            if (lane < 8) {
                float v = ALt[src * 8 + lane] + arh;
                v = v > 0.f ? v : 0.2f * v;
                p8 = expf(v - m) * inv_s;
            }
            float a = __shfl_sync(0xffffffffu, p8, hsrc);
            float4 xv = *(const float4*)&XWt[(size_t)src * DD + lane * 4];
            acc.x += xv.x * a; acc.y += xv.y * a; acc.z += xv.z * a; acc.w += xv.w * a;
        }
    }

    int c = lane * 4;
#pragma unroll
    for (int t = 0; t < TT; t++) {
        float4 bb = *(const float4*)&b[t * DD + c];
        acc.x += bb.x; acc.y += bb.y; acc.z += bb.z; acc.w += bb.w;
    }
    float ss = acc.x * acc.x + acc.y * acc.y + acc.z * acc.z + acc.w * acc.w;
#pragma unroll
    for (int o = 16; o; o >>= 1) ss += __shfl_xor_sync(0xffffffffu, ss, o);
    float r = rsqrtf(ss * (1.0f / DD) + 1e-6f);
    float4 gg = *(const float4*)&g[c];
    float4 hv = *(const float4*)&H[(size_t)n * DD + c];
    float4 ov;
    ov.x = gelu_f(hv.x + gg.x * acc.x * r);
    ov.y = gelu_f(hv.y + gg.y * acc.y * r);
    ov.z = gelu_f(hv.z + gg.z * acc.z * r);
    ov.w = gelu_f(hv.w + gg.w * acc.w * r);
    *(float4*)&H[(size_t)n * DD + c] = ov;
}

// ---------------- HGT ----------------
// KA[t][n, h*16+f] = sum_d K[n, h*16+d] * arel[t][h,d,f]   (and VM from V, mrel)
__global__ void hgt_rel4(const float* __restrict__ K, const float* __restrict__ V,
                         const float* __restrict__ arel, const float* __restrict__ mrel,
                         float* __restrict__ KA, float* __restrict__ VM)
{
    int t = blockIdx.y;
    int isV = blockIdx.z;
    const float* X = isV ? V : K;
    const float* R = (isV ? mrel : arel) + t * 2048;
    float* Y = (isV ? VM : KA) + (size_t)t * ND;
    int g = blockIdx.x * blockDim.x + threadIdx.x;
    if (g >= ND) return;
    int n = g >> 7, c = g & 127, h = c >> 4, f = c & 15;
    const float* xp = X + (size_t)n * DD + h * 16;
    const float* rp = R + h * 256 + f;
    float acc = 0.f;
#pragma unroll
    for (int d = 0; d < 16; d++) acc += xp[d] * rp[d * 16];
    Y[g] = acc;
}

__global__ void hgt_att4(const int* __restrict__ e0, const int* __restrict__ e1,
                         const int* __restrict__ e2, const int* __restrict__ e3,
                         const float* __restrict__ Q, const float* __restrict__ KA,
                         const float* __restrict__ prel, float* __restrict__ ATT)
{
    int t = blockIdx.y;
    const int* ei = t == 0 ? e0 : t == 1 ? e1 : t == 2 ? e2 : e3;
    int g = blockIdx.x * blockDim.x + threadIdx.x;
    if (g >= EE * 8) return;
    int e = g >> 3, h = g & 7;
    int src = ei[e], dst = ei[EE + e];
    const float* qp = Q + (size_t)dst * DD + h * 16;
    const float* kp = KA + (size_t)t * ND + (size_t)src * DD + h * 16;
    float acc = 0.f;
#pragma unroll
    for (int f = 0; f < 16; f++) acc += qp[f] * kp[f];
    ATT[(size_t)t * EE * 8 + g] = acc * prel[t * 8 + h] * 0.25f;
}

// Fused HGT aggregation: joint softmax across types, weighted VM gather, gelu.
__global__ __launch_bounds__(256) void hgt_agg(
    const int* __restrict__ rowptr, const int* __restrict__ csrc, const int* __restrict__ ceid,
    const float* __restrict__ ATT, const float* __restrict__ VM4, float* __restrict__ TMP)
{
    int n = (blockIdx.x * blockDim.x + threadIdx.x) >> 5;
    if (n >= NN) return;
    int lane = threadIdx.x & 31;
    int hsrc = lane >> 2;

    float m = -1e30f;
    for (int t = 0; t < TT; t++) {
        int beg = rowptr[t * (NN + 1) + n], end = rowptr[t * (NN + 1) + n + 1];
        for (int p = beg; p < end; p++) {
            int e = ceid[t * EE + p];
            if (lane < 8) m = fmaxf(m, ATT[(size_t)t * EE * 8 + (size_t)e * 8 + lane]);
        }
    }
    float s = 0.f;
    for (int t = 0; t < TT; t++) {
        int beg = rowptr[t * (NN + 1) + n], end = rowptr[t * (NN + 1) + n + 1];
        for (int p = beg; p < end; p++) {
            int e = ceid[t * EE + p];
            if (lane < 8) s += expf(ATT[(size_t)t * EE * 8 + (size_t)e * 8 + lane] - m);
        }
    }
    float inv_s = (lane < 8 && s > 0.f) ? 1.0f / s : 0.f;
    float4 acc = make_float4(0.f, 0.f, 0.f, 0.f);
    for (int t = 0; t < TT; t++) {
        int beg = rowptr[t * (NN + 1) + n], end = rowptr[t * (NN + 1) + n + 1];
        for (int p = beg; p < end; p++) {
            int e = ceid[t * EE + p];
            int src = csrc[t * EE + p];
            float p8 = 0.f;
            if (lane < 8) p8 = expf(ATT[(size_t)t * EE * 8 + (size_t)e * 8 + lane] - m) * inv_s;
            float a = __shfl_sync(0xffffffffu, p8, hsrc);
            float4 xv = *(const float4*)&VM4[(size_t)t * ND + (size_t)src * DD + lane * 4];
            acc.x += xv.x * a; acc.y += xv.y * a; acc.z += xv.z * a; acc.w += xv.w * a;
        }
    }
    int c = lane * 4;
    float4 ov;
    ov.x = gelu_f(acc.x);
    ov.y = gelu_f(acc.y);
    ov.z = gelu_f(acc.z);
    ov.w = gelu_f(acc.w);
    *(float4*)&TMP[(size_t)n * DD + c] = ov;
}

// out = gelu(H + rmsnorm(beta*OUT2 + (1-beta)*H, g3)), warp per node
__global__ __launch_bounds__(256) void finalize_hgt(
    const float* __restrict__ H, const float* __restrict__ OUT2,
    const float* __restrict__ skip, const float* __restrict__ g3,
    float* __restrict__ out)
{
    int n = (blockIdx.x * blockDim.x + threadIdx.x) >> 5;
    if (n >= NN) return;
    int lane = threadIdx.x & 31;
    int c = lane * 4;
    float beta = 1.0f / (1.0f + expf(-skip[0]));
    float4 hv = *(const float4*)&H[(size_t)n * DD + c];
    float4 o2 = *(const float4*)&OUT2[(size_t)n * DD + c];
    float4 y;
    y.x = beta * o2.x + (1.f - beta) * hv.x;
    y.y = beta * o2.y + (1.f - beta) * hv.y;
    y.z = beta * o2.z + (1.f - beta) * hv.z;
    y.w = beta * o2.w + (1.f - beta) * hv.w;
    float ss = y.x * y.x + y.y * y.y + y.z * y.z + y.w * y.w;
#pragma unroll
    for (int o = 16; o; o >>= 1) ss += __shfl_xor_sync(0xffffffffu, ss, o);
    float r = rsqrtf(ss * (1.0f / DD) + 1e-6f);
    float4 gg = *(const float4*)&g3[c];
    float4 ov;
    ov.x = gelu_f(hv.x + gg.x * y.x * r);
    ov.y = gelu_f(hv.y + gg.y * y.y * r);
    ov.z = gelu_f(hv.z + gg.z * y.z * r);
    ov.w = gelu_f(hv.w + gg.w * y.w * r);
    *(float4*)&out[(size_t)n * DD + c] = ov;
}

// ---------------- driver ----------------
extern "C" void kernel_launch(void* const* d_in, const int* in_sizes, int n_in,
                              void* d_out, int out_size)
{
    const float* zL  = (const float*)d_in[0];
    const float* zH  = (const float*)d_in[1];
    const float* xe  = (const float*)d_in[2];
    const float* W1  = (const float*)d_in[3];
    const float* as1 = (const float*)d_in[4];
    const float* ad1 = (const float*)d_in[5];
    const float* b1  = (const float*)d_in[6];
    const float* W2  = (const float*)d_in[7];
    const float* as2 = (const float*)d_in[8];
    const float* ad2 = (const float*)d_in[9];
    const float* b2  = (const float*)d_in[10];
    const float* Wk  = (const float*)d_in[11];
    const float* bk  = (const float*)d_in[12];
    const float* Wq  = (const float*)d_in[13];
    const float* bq  = (const float*)d_in[14];
    const float* Wv  = (const float*)d_in[15];
    const float* bv  = (const float*)d_in[16];
    const float* arel= (const float*)d_in[17];
    const float* mrel= (const float*)d_in[18];
    const float* prel= (const float*)d_in[19];
    const float* Wo  = (const float*)d_in[20];
    const float* bo  = (const float*)d_in[21];
    const float* skip= (const float*)d_in[22];
    const float* g1  = (const float*)d_in[23];
    const float* g2  = (const float*)d_in[24];
    const float* g3  = (const float*)d_in[25];
    const int* e0 = (const int*)d_in[26];
    const int* e1 = (const int*)d_in[27];
    const int* e2 = (const int*)d_in[28];
    const int* e3 = (const int*)d_in[29];

    float* SB = nullptr;
    cudaGetSymbolAddress((void**)&SB, d_scratch);
    float* H    = SB;
    float* Q    = SB + (size_t)ND;
    float* K    = SB + 2 * (size_t)ND;
    float* V    = SB + 3 * (size_t)ND;
    float* TMP  = SB + 4 * (size_t)ND;
    float* XW4  = SB + 5 * (size_t)ND;   // 4*ND; reused as KA after GAT
    float* VM4  = SB + 9 * (size_t)ND;   // 4*ND
    float* AL   = SB + 13 * (size_t)ND;            // 4*N*8
    float* AR   = AL + 4 * (size_t)NN * 8;         // 4*N*8
    float* ATT  = AR + 4 * (size_t)NN * 8;         // 4*E*8
    int*   IB   = (int*)(ATT + 4 * (size_t)EE * 8);
    int* deg    = IB;
    int* rowptr = IB + 4 * NN;
    int* wofs   = rowptr + 4 * (NN + 1);
    int* csrc   = wofs + 4 * NN;
    int* ceid   = csrc + 4 * EE;

    const int TPB = 256;
    const int gND  = (ND + TPB - 1) / TPB;
    const int gN8  = (NN * 8 + TPB - 1) / TPB;
    const int gE8  = (EE * 8 + TPB - 1) / TPB;
    const int g4E  = (4 * EE + TPB - 1) / TPB;
    const int g4N  = (4 * NN + TPB - 1) / TPB;
    const int gGEMM = (NN + 127) / 128;
    const int gWARP = (NN * 32 + TPB - 1) / TPB;   // warp-per-node kernels

    // input sum
    add3_k<<<gND, TPB>>>(zL, zH, xe, H);

    // CSR build (4 edge types), reused by GAT L1, GAT L2, HGT
    cudaMemsetAsync(deg, 0, 4 * NN * sizeof(int));
    deg_count<<<g4E, TPB>>>(e0, e1, e2, e3, deg);
    scan_k<<<4, 1024>>>(deg, rowptr);
    wofs_init<<<g4N, TPB>>>(rowptr, wofs);
    csr_fill<<<g4E, TPB>>>(e0, e1, e2, e3, wofs, csrc, ceid);

    // GAT layers
    const float* Ws[2]  = {W1, W2};
    const float* ass[2] = {as1, as2};
    const float* ads[2] = {ad1, ad2};
    const float* bs[2]  = {b1, b2};
    const float* gs[2]  = {g1, g2};
    for (int L = 0; L < 2; L++) {
        for (int t = 0; t < TT; t++)
            gemm128<<<gGEMM, 256>>>(H, Ws[L] + (size_t)t * DD * DD, nullptr,
                                    XW4 + (size_t)t * ND, NN);
        {
            dim3 gr(gN8, 4);
            gat_alr4<<<gr, TPB>>>(XW4, ass[L], ads[L], AL, AR);
        }
        gat_agg<<<gWARP, TPB>>>(rowptr, csrc, AL, AR, XW4, bs[L], gs[L], H);
    }

    // HGT
    gemm128<<<gGEMM, 256>>>(H, Wk, bk, K, NN);
    gemm128<<<gGEMM, 256>>>(H, Wq, bq, Q, NN);
    gemm128<<<gGEMM, 256>>>(H, Wv, bv, V, NN);
    {
        dim3 gr(gND, 4, 2);
        hgt_rel4<<<gr, TPB>>>(K, V, arel, mrel, XW4 /*KA*/, VM4);
    }
    {
        dim3 gr(gE8, 4);
        hgt_att4<<<gr, TPB>>>(e0, e1, e2, e3, Q, XW4 /*KA*/, prel, ATT);
    }
    hgt_agg<<<gWARP, TPB>>>(rowptr, csrc, ceid, ATT, VM4, TMP);
    gemm128<<<gGEMM, 256>>>(TMP, Wo, bo, V /*reuse as OUT2*/, NN);
    finalize_hgt<<<gWARP, TPB>>>(H, V, skip, g3, (float*)d_out);
}

// round 8
// speedup vs baseline: 2.0757x; 1.4886x over previous
#include <cuda_runtime.h>
#include <math.h>

#define NN 50000
#define DD 128
#define TT 4
#define EE 150000
#define ND (NN*DD)

__device__ float d_scratch[104000000];

__device__ __forceinline__ float gelu_f(float x) {
    return 0.5f * x * (1.0f + erff(x * 0.7071067811865476f));
}

// ---------------- elementwise ----------------
__global__ void add3_k(const float* __restrict__ a, const float* __restrict__ b,
                       const float* __restrict__ c, float* __restrict__ o) {
    int i = blockIdx.x * blockDim.x + threadIdx.x;
    if (i < ND) o[i] = a[i] + b[i] + c[i];
}

__global__ void fill0_k(int* __restrict__ p, int n) {
    int i = blockIdx.x * blockDim.x + threadIdx.x;
    if (i < n) p[i] = 0;
}

// ---------------- CSR build ----------------
__global__ void deg_count(const int* __restrict__ e0, const int* __restrict__ e1,
                          const int* __restrict__ e2, const int* __restrict__ e3,
                          int* __restrict__ deg) {
    int g = blockIdx.x * blockDim.x + threadIdx.x;
    if (g >= 4 * EE) return;
    int t = g / EE, e = g - t * EE;
    const int* ei = t == 0 ? e0 : t == 1 ? e1 : t == 2 ? e2 : e3;
    atomicAdd(deg + t * NN + ei[EE + e], 1);
}

__global__ void scan_k(const int* __restrict__ deg, int* __restrict__ rowptr,
                       int* __restrict__ wofs) {
    int t = blockIdx.x;
    const int* d = deg + t * NN;
    int* rp = rowptr + t * (NN + 1);
    __shared__ int warpsum[32];
    __shared__ int s_carry;
    if (threadIdx.x == 0) { rp[0] = 0; s_carry = 0; }
    __syncthreads();
    int lane = threadIdx.x & 31, wid = threadIdx.x >> 5;
    for (int base = 0; base < NN; base += 1024) {
        int i = base + (int)threadIdx.x;
        int v = (i < NN) ? d[i] : 0;
        int x = v;
#pragma unroll
        for (int o = 1; o < 32; o <<= 1) {
            int y = __shfl_up_sync(0xffffffffu, x, o);
            if (lane >= o) x += y;
        }
        if (lane == 31) warpsum[wid] = x;
        __syncthreads();
        if (wid == 0) {
            int w = warpsum[lane];
#pragma unroll
            for (int o = 1; o < 32; o <<= 1) {
                int y = __shfl_up_sync(0xffffffffu, w, o);
                if (lane >= o) w += y;
            }
            warpsum[lane] = w;
        }
        __syncthreads();
        int incl = x + (wid > 0 ? warpsum[wid - 1] : 0) + s_carry;
        if (i < NN) { rp[i + 1] = incl; wofs[t * NN + i] = incl - v; }
        __syncthreads();
        if (threadIdx.x == 1023) s_carry = incl;
        __syncthreads();
    }
}

__global__ void csr_fill(const int* __restrict__ e0, const int* __restrict__ e1,
                         const int* __restrict__ e2, const int* __restrict__ e3,
                         int* __restrict__ wofs, int* __restrict__ csrc) {
    int g = blockIdx.x * blockDim.x + threadIdx.x;
    if (g >= 4 * EE) return;
    int t = g / EE, e = g - t * EE;
    const int* ei = t == 0 ? e0 : t == 1 ? e1 : t == 2 ? e2 : e3;
    int src = ei[e], dst = ei[EE + e];
    int pos = atomicAdd(wofs + t * NN + dst, 1);
    csrc[t * EE + pos] = src;
}

// ---------------- batched GEMM core: C = A @ B (+bias), K-chunk 16, FFMA2 ----------------
__device__ __forceinline__ void gemm_body(
    const float* __restrict__ A, const float* __restrict__ B,
    const float* __restrict__ bias, float* __restrict__ C, int Mrows)
{
    __shared__ float As[16][132];
    __shared__ float Bs[16][128];
    const int tid = threadIdx.x;
    const int tx = tid & 15;
    const int ty = tid >> 4;
    const int rbase = blockIdx.x * 128;

    unsigned long long acc[8][4];
#pragma unroll
    for (int i = 0; i < 8; i++)
#pragma unroll
        for (int j = 0; j < 4; j++) acc[i][j] = 0ull;

    const int arow = tid >> 1;
    const int aq   = (tid & 1) * 8;
    const int bk   = tid >> 4;        // 0..15
    const int bc   = (tid & 15) * 8;

    for (int k0 = 0; k0 < 128; k0 += 16) {
        float4 av0 = make_float4(0.f, 0.f, 0.f, 0.f), av1 = av0;
        int r = rbase + arow;
        if (r < Mrows) {
            av0 = *(const float4*)&A[(size_t)r * 128 + k0 + aq];
            av1 = *(const float4*)&A[(size_t)r * 128 + k0 + aq + 4];
        }
        As[aq + 0][arow] = av0.x; As[aq + 1][arow] = av0.y;
        As[aq + 2][arow] = av0.z; As[aq + 3][arow] = av0.w;
        As[aq + 4][arow] = av1.x; As[aq + 5][arow] = av1.y;
        As[aq + 6][arow] = av1.z; As[aq + 7][arow] = av1.w;
        *(float4*)&Bs[bk][bc]     = *(const float4*)&B[(size_t)(k0 + bk) * 128 + bc];
        *(float4*)&Bs[bk][bc + 4] = *(const float4*)&B[(size_t)(k0 + bk) * 128 + bc + 4];
        __syncthreads();
#pragma unroll
        for (int k = 0; k < 16; k++) {
            float a[8];
            *(float4*)&a[0] = *(const float4*)&As[k][ty * 8];
            *(float4*)&a[4] = *(const float4*)&As[k][ty * 8 + 4];
            unsigned long long bp[4];
            ulonglong2 b01 = *(const ulonglong2*)&Bs[k][tx * 8];
            ulonglong2 b23 = *(const ulonglong2*)&Bs[k][tx * 8 + 4];
            bp[0] = b01.x; bp[1] = b01.y; bp[2] = b23.x; bp[3] = b23.y;
#pragma unroll
            for (int i = 0; i < 8; i++) {
                unsigned long long ap;
                asm("mov.b64 %0, {%1, %1};" : "=l"(ap) : "f"(a[i]));
#pragma unroll
                for (int j = 0; j < 4; j++)
                    asm("fma.rn.f32x2 %0, %1, %2, %0;" : "+l"(acc[i][j]) : "l"(ap), "l"(bp[j]));
            }
        }
        __syncthreads();
    }

    float bb[8];
#pragma unroll
    for (int j = 0; j < 8; j++) bb[j] = bias ? bias[tx * 8 + j] : 0.0f;

#pragma unroll
    for (int i = 0; i < 8; i++) {
        int r = rbase + ty * 8 + i;
        if (r < Mrows) {
            float o[8];
#pragma unroll
            for (int j = 0; j < 4; j++) {
                float lo, hi;
                asm("mov.b64 {%0, %1}, %2;" : "=f"(lo), "=f"(hi) : "l"(acc[i][j]));
                o[2 * j]     = lo + bb[2 * j];
                o[2 * j + 1] = hi + bb[2 * j + 1];
            }
            *(float4*)&C[(size_t)r * 128 + tx * 8]     = make_float4(o[0], o[1], o[2], o[3]);
            *(float4*)&C[(size_t)r * 128 + tx * 8 + 4] = make_float4(o[4], o[5], o[6], o[7]);
        }
    }
}

// GAT: B slices contiguous at Wbase + y*16384, C slices at Cbase + y*ND, no bias
__global__ __launch_bounds__(256) void gemm_gat(
    const float* __restrict__ A, const float* __restrict__ Wbase,
    float* __restrict__ Cbase, int Mrows)
{
    gemm_body(A, Wbase + (size_t)blockIdx.y * 16384, nullptr,
              Cbase + (size_t)blockIdx.y * ND, Mrows);
}

// up-to-3 distinct B/bias, C slices at Cbase + y*ND
__global__ __launch_bounds__(256) void gemm3(
    const float* __restrict__ A,
    const float* __restrict__ B0, const float* __restrict__ B1, const float* __restrict__ B2,
    const float* __restrict__ c0, const float* __restrict__ c1, const float* __restrict__ c2,
    float* __restrict__ Cbase, int Mrows)
{
    int y = blockIdx.y;
    const float* B = y == 0 ? B0 : y == 1 ? B1 : B2;
    const float* bias = y == 0 ? c0 : y == 1 ? c1 : c2;
    gemm_body(A, B, bias, Cbase + (size_t)y * ND, Mrows);
}

// ---------------- GAT ----------------
__global__ void gat_alr4(const float* __restrict__ XW4,
                         const float* __restrict__ asrc, const float* __restrict__ adst,
                         float* __restrict__ AL, float* __restrict__ AR)
{
    int t = blockIdx.y;
    int g = blockIdx.x * blockDim.x + threadIdx.x;
    if (g >= NN * 8) return;
    int i = g >> 3, h = g & 7;
    const float* xp = XW4 + (size_t)t * ND + (size_t)i * DD + h * 16;
    const float* ap = asrc + t * DD + h * 16;
    const float* bp = adst + t * DD + h * 16;
    float s1 = 0.f, s2 = 0.f;
#pragma unroll
    for (int q = 0; q < 4; q++) {
        float4 xv = *(const float4*)&xp[q * 4];
        float4 aa = *(const float4*)&ap[q * 4];
        float4 dd = *(const float4*)&bp[q * 4];
        s1 += xv.x * aa.x + xv.y * aa.y + xv.z * aa.z + xv.w * aa.w;
        s2 += xv.x * dd.x + xv.y * dd.y + xv.z * dd.z + xv.w * dd.w;
    }
    AL[t * NN * 8 + g] = s1;
    AR[t * NN * 8 + g] = s2;
}

// Fused per-dst GAT aggregation: single-pass online softmax per type,
// + bias + rmsnorm + residual + gelu. One warp per node. Updates H in place.
__global__ __launch_bounds__(256) void gat_agg(
    const int* __restrict__ rowptr, const int* __restrict__ csrc,
    const float* __restrict__ AL, const float* __restrict__ AR,
    const float* __restrict__ XW4,
    const float* __restrict__ b, const float* __restrict__ g,
    float* __restrict__ H)
{
    int n = (blockIdx.x * blockDim.x + threadIdx.x) >> 5;
    if (n >= NN) return;
    int lane = threadIdx.x & 31;
    int hsrc = lane >> 2;
    float4 tot = make_float4(0.f, 0.f, 0.f, 0.f);

    for (int t = 0; t < TT; t++) {
        const float* ALt = AL + (size_t)t * NN * 8;
        const float* ARt = AR + (size_t)t * NN * 8;
        const float* XWt = XW4 + (size_t)t * ND;
        int beg = rowptr[t * (NN + 1) + n];
        int end = rowptr[t * (NN + 1) + n + 1];

        // all lanes track their head's state (replicated within 4-lane groups)
        float arh = ARt[n * 8 + hsrc];
        float vs = ALt[n * 8 + hsrc] + arh;
        vs = vs > 0.f ? vs : 0.2f * vs;
        float m = vs, s = 1.0f;                 // self-loop: weight exp(0)=1
        float4 acc = *(const float4*)&XWt[(size_t)n * DD + lane * 4];

        for (int p = beg; p < end; p++) {
            int src = csrc[t * EE + p];
            float v = ALt[src * 8 + hsrc] + arh;
            v = v > 0.f ? v : 0.2f * v;
            float mn = fmaxf(m, v);
            float sc = __expf(m - mn) ;
            float pw = __expf(v - mn);
            // use precise expf to stay bit-close? fp32 expf fine:
            sc = expf(m - mn); pw = expf(v - mn);
            s = s * sc + pw;
            m = mn;
            float4 xv = *(const float4*)&XWt[(size_t)src * DD + lane * 4];
            acc.x = acc.x * sc + xv.x * pw;
            acc.y = acc.y * sc + xv.y * pw;
            acc.z = acc.z * sc + xv.z * pw;
            acc.w = acc.w * sc + xv.w * pw;
        }
        float inv = 1.0f / s;
        tot.x += acc.x * inv; tot.y += acc.y * inv;
        tot.z += acc.z * inv; tot.w += acc.w * inv;
    }

    int c = lane * 4;
#pragma unroll
    for (int t = 0; t < TT; t++) {
        float4 bb = *(const float4*)&b[t * DD + c];
        tot.x += bb.x; tot.y += bb.y; tot.z += bb.z; tot.w += bb.w;
    }
    float ss = tot.x * tot.x + tot.y * tot.y + tot.z * tot.z + tot.w * tot.w;
#pragma unroll
    for (int o = 16; o; o >>= 1) ss += __shfl_xor_sync(0xffffffffu, ss, o);
    float r = rsqrtf(ss * (1.0f / DD) + 1e-6f);
    float4 gg = *(const float4*)&g[c];
    float4 hv = *(const float4*)&H[(size_t)n * DD + c];
    float4 ov;
    ov.x = gelu_f(hv.x + gg.x * tot.x * r);
    ov.y = gelu_f(hv.y + gg.y * tot.y * r);
    ov.z = gelu_f(hv.z + gg.z * tot.z * r);
    ov.w = gelu_f(hv.w + gg.w * tot.w * r);
    *(float4*)&H[(size_t)n * DD + c] = ov;
}

// ---------------- HGT ----------------
// KA[t][n, h*16+f] = sum_d K[n,h*16+d]*arel[t,h,d,f]; VM likewise. 2 outputs/thread.
__global__ void hgt_rel2(const float* __restrict__ K, const float* __restrict__ V,
                         const float* __restrict__ arel, const float* __restrict__ mrel,
                         float* __restrict__ KA, float* __restrict__ VM)
{
    int t = blockIdx.y, isV = blockIdx.z;
    const float* X = isV ? V : K;
    const float* R = (isV ? mrel : arel) + t * 2048;
    float* Y = (isV ? VM : KA) + (size_t)t * ND;
    int g = blockIdx.x * blockDim.x + threadIdx.x;   // output-pair index
    if (g >= ND / 2) return;
    int n = g >> 6, c2 = g & 63, h = c2 >> 3, f0 = (c2 & 7) * 2;
    const float* xp = X + (size_t)n * DD + h * 16;
    const float* rp = R + h * 256 + f0;
    float xv[16];
#pragma unroll
    for (int q = 0; q < 4; q++) *(float4*)&xv[q * 4] = *(const float4*)&xp[q * 4];
    unsigned long long acc = 0ull;
#pragma unroll
    for (int d = 0; d < 16; d++) {
        unsigned long long xb, rb;
        asm("mov.b64 %0, {%1, %1};" : "=l"(xb) : "f"(xv[d]));
        rb = *(const unsigned long long*)&rp[d * 16];
        asm("fma.rn.f32x2 %0, %1, %2, %0;" : "+l"(acc) : "l"(xb), "l"(rb));
    }
    *(unsigned long long*)&Y[(size_t)n * DD + h * 16 + f0] = acc;
}

// Fused HGT attention + aggregation: joint online softmax across all 4 types.
// One warp per node. Writes gelu(agg) to TMP.
__global__ __launch_bounds__(256) void hgt_fused(
    const int* __restrict__ rowptr, const int* __restrict__ csrc,
    const float* __restrict__ Q, const float* __restrict__ KA4,
    const float* __restrict__ VM4, const float* __restrict__ prel,
    float* __restrict__ TMP)
{
    int n = (blockIdx.x * blockDim.x + threadIdx.x) >> 5;
    if (n >= NN) return;
    int lane = threadIdx.x & 31;
    int hsrc = lane >> 2;

    float4 qv = *(const float4*)&Q[(size_t)n * DD + lane * 4];
    float m = -1e30f, s = 0.f;
    float4 acc = make_float4(0.f, 0.f, 0.f, 0.f);

    for (int t = 0; t < TT; t++) {
        const float* KAt = KA4 + (size_t)t * ND;
        const float* VMt = VM4 + (size_t)t * ND;
        float pr = prel[t * 8 + hsrc] * 0.25f;
        int beg = rowptr[t * (NN + 1) + n];
        int end = rowptr[t * (NN + 1) + n + 1];
        for (int p = beg; p < end; p++) {
            int src = csrc[t * EE + p];
            float4 ka = *(const float4*)&KAt[(size_t)src * DD + lane * 4];
            float d = qv.x * ka.x + qv.y * ka.y + qv.z * ka.z + qv.w * ka.w;
            d += __shfl_xor_sync(0xffffffffu, d, 1);
            d += __shfl_xor_sync(0xffffffffu, d, 2);   // per-head 16-dot, replicated
            float l = d * pr;
            float mn = fmaxf(m, l);
            float sc = expf(m - mn);
            float pw = expf(l - mn);
            s = s * sc + pw;
            m = mn;
            float4 vm = *(const float4*)&VMt[(size_t)src * DD + lane * 4];
            acc.x = acc.x * sc + vm.x * pw;
            acc.y = acc.y * sc + vm.y * pw;
            acc.z = acc.z * sc + vm.z * pw;
            acc.w = acc.w * sc + vm.w * pw;
        }
    }
    float inv = (s > 0.f) ? 1.0f / s : 0.f;
    int c = lane * 4;
    float4 ov;
    ov.x = gelu_f(acc.x * inv);
    ov.y = gelu_f(acc.y * inv);
    ov.z = gelu_f(acc.z * inv);
    ov.w = gelu_f(acc.w * inv);
    *(float4*)&TMP[(size_t)n * DD + c] = ov;
}

// out = gelu(H + rmsnorm(beta*OUT2 + (1-beta)*H, g3)), warp per node
__global__ __launch_bounds__(256) void finalize_hgt(
    const float* __restrict__ H, const float* __restrict__ OUT2,
    const float* __restrict__ skip, const float* __restrict__ g3,
    float* __restrict__ out)
{
    int n = (blockIdx.x * blockDim.x + threadIdx.x) >> 5;
    if (n >= NN) return;
    int lane = threadIdx.x & 31;
    int c = lane * 4;
    float beta = 1.0f / (1.0f + expf(-skip[0]));
    float4 hv = *(const float4*)&H[(size_t)n * DD + c];
    float4 o2 = *(const float4*)&OUT2[(size_t)n * DD + c];
    float4 y;
    y.x = beta * o2.x + (1.f - beta) * hv.x;
    y.y = beta * o2.y + (1.f - beta) * hv.y;
    y.z = beta * o2.z + (1.f - beta) * hv.z;
    y.w = beta * o2.w + (1.f - beta) * hv.w;
    float ss = y.x * y.x + y.y * y.y + y.z * y.z + y.w * y.w;
#pragma unroll
    for (int o = 16; o; o >>= 1) ss += __shfl_xor_sync(0xffffffffu, ss, o);
    float r = rsqrtf(ss * (1.0f / DD) + 1e-6f);
    float4 gg = *(const float4*)&g3[c];
    float4 ov;
    ov.x = gelu_f(hv.x + gg.x * y.x * r);
    ov.y = gelu_f(hv.y + gg.y * y.y * r);
    ov.z = gelu_f(hv.z + gg.z * y.z * r);
    ov.w = gelu_f(hv.w + gg.w * y.w * r);
    *(float4*)&out[(size_t)n * DD + c] = ov;
}

// ---------------- driver ----------------
extern "C" void kernel_launch(void* const* d_in, const int* in_sizes, int n_in,
                              void* d_out, int out_size)
{
    const float* zL  = (const float*)d_in[0];
    const float* zH  = (const float*)d_in[1];
    const float* xe  = (const float*)d_in[2];
    const float* W1  = (const float*)d_in[3];
    const float* as1 = (const float*)d_in[4];
    const float* ad1 = (const float*)d_in[5];
    const float* b1  = (const float*)d_in[6];
    const float* W2  = (const float*)d_in[7];
    const float* as2 = (const float*)d_in[8];
    const float* ad2 = (const float*)d_in[9];
    const float* b2  = (const float*)d_in[10];
    const float* Wk  = (const float*)d_in[11];
    const float* bk  = (const float*)d_in[12];
    const float* Wq  = (const float*)d_in[13];
    const float* bq  = (const float*)d_in[14];
    const float* Wv  = (const float*)d_in[15];
    const float* bv  = (const float*)d_in[16];
    const float* arel= (const float*)d_in[17];
    const float* mrel= (const float*)d_in[18];
    const float* prel= (const float*)d_in[19];
    const float* Wo  = (const float*)d_in[20];
    const float* bo  = (const float*)d_in[21];
    const float* skip= (const float*)d_in[22];
    const float* g1  = (const float*)d_in[23];
    const float* g2  = (const float*)d_in[24];
    const float* g3  = (const float*)d_in[25];
    const int* e0 = (const int*)d_in[26];
    const int* e1 = (const int*)d_in[27];
    const int* e2 = (const int*)d_in[28];
    const int* e3 = (const int*)d_in[29];

    float* SB = nullptr;
    cudaGetSymbolAddress((void**)&SB, d_scratch);
    float* H    = SB;
    float* Q    = SB + (size_t)ND;       // Q,K,V contiguous (gemm3 Cbase)
    float* K    = SB + 2 * (size_t)ND;
    float* V    = SB + 3 * (size_t)ND;
    float* TMP  = SB + 4 * (size_t)ND;
    float* XW4  = SB + 5 * (size_t)ND;   // 4 slices; reused as KA4 after GAT
    float* VM4  = SB + 9 * (size_t)ND;   // 4 slices
    float* AL   = SB + 13 * (size_t)ND;
    float* AR   = AL + 4 * (size_t)NN * 8;
    int*   IB   = (int*)(AR + 4 * (size_t)NN * 8);
    int* deg    = IB;
    int* rowptr = IB + 4 * NN;
    int* wofs   = rowptr + 4 * (NN + 1);
    int* csrc   = wofs + 4 * NN;

    const int TPB  = 256;
    const int gND  = (ND + TPB - 1) / TPB;
    const int gN8  = (NN * 8 + TPB - 1) / TPB;
    const int g4E  = (4 * EE + TPB - 1) / TPB;
    const int g4N  = (4 * NN + TPB - 1) / TPB;
    const int gGEMM = (NN + 127) / 128;
    const int gWARP = (NN * 32 + TPB - 1) / TPB;

    // 1..5: input sum + CSR build (reused by GAT L1, L2, HGT)
    add3_k<<<gND, TPB>>>(zL, zH, xe, H);
    fill0_k<<<g4N, TPB>>>(deg, 4 * NN);
    deg_count<<<g4E, TPB>>>(e0, e1, e2, e3, deg);
    scan_k<<<4, 1024>>>(deg, rowptr, wofs);
    csr_fill<<<g4E, TPB>>>(e0, e1, e2, e3, wofs, csrc);

    // GAT layers (launch 6 = batched GEMM, lands in ncu window)
    const float* Ws[2]  = {W1, W2};
    const float* ass[2] = {as1, as2};
    const float* ads[2] = {ad1, ad2};
    const float* bs[2]  = {b1, b2};
    const float* gs[2]  = {g1, g2};
    for (int L = 0; L < 2; L++) {
        dim3 gg(gGEMM, 4);
        gemm_gat<<<gg, 256>>>(H, Ws[L], XW4, NN);
        dim3 ga(gN8, 4);
        gat_alr4<<<ga, TPB>>>(XW4, ass[L], ads[L], AL, AR);
        gat_agg<<<gWARP, TPB>>>(rowptr, csrc, AL, AR, XW4, bs[L], gs[L], H);
    }

    // HGT: Q,K,V in one batched launch
    {
        dim3 gg(gGEMM, 3);
        gemm3<<<gg, 256>>>(H, Wq, Wk, Wv, bq, bk, bv, Q, NN);
    }
    {
        dim3 gr((ND / 2 + TPB - 1) / TPB, 4, 2);
        hgt_rel2<<<gr, TPB>>>(K, V, arel, mrel, XW4 /*KA4*/, VM4);
    }
    hgt_fused<<<gWARP, TPB>>>(rowptr, csrc, Q, XW4, VM4, prel, TMP);
    {
        dim3 gg(gGEMM, 1);
        gemm3<<<gg, 256>>>(TMP, Wo, Wo, Wo, bo, bo, bo, K /*OUT2*/, NN);
    }
    finalize_hgt<<<gWARP, TPB>>>(H, K, skip, g3, (float*)d_out);
}

// round 10
// speedup vs baseline: 2.3006x; 1.1083x over previous
#include <cuda_runtime.h>
#include <math.h>

#define NN 50000
#define DD 128
#define TT 4
#define EE 150000
#define ND (NN*DD)
#define NBLK 49   // ceil(NN/1024)

__device__ float d_scratch[104000000];

__device__ __forceinline__ float gelu_f(float x) {
    return 0.5f * x * (1.0f + erff(x * 0.7071067811865476f));
}

// ---------------- elementwise ----------------
__global__ void add3_k(const float* __restrict__ a, const float* __restrict__ b,
                       const float* __restrict__ c, float* __restrict__ o) {
    int i = blockIdx.x * blockDim.x + threadIdx.x;
    if (i < ND) o[i] = a[i] + b[i] + c[i];
}

__global__ void fill0_k(int* __restrict__ p, int n) {
    int i = blockIdx.x * blockDim.x + threadIdx.x;
    if (i < n) p[i] = 0;
}

// ---------------- CSR build ----------------
__global__ void deg_count(const int* __restrict__ e0, const int* __restrict__ e1,
                          const int* __restrict__ e2, const int* __restrict__ e3,
                          int* __restrict__ deg) {
    int g = blockIdx.x * blockDim.x + threadIdx.x;
    if (g >= 4 * EE) return;
    int t = g / EE, e = g - t * EE;
    const int* ei = t == 0 ? e0 : t == 1 ? e1 : t == 2 ? e2 : e3;
    atomicAdd(deg + t * NN + ei[EE + e], 1);
}

// phase 1: per-1024-chunk inclusive scan, chunk totals to bsum
__global__ void scan1(const int* __restrict__ deg, int* __restrict__ rowptr,
                      int* __restrict__ bsum) {
    int t = blockIdx.y, b = blockIdx.x;
    int i = b * 1024 + (int)threadIdx.x;
    int v = (i < NN) ? deg[t * NN + i] : 0;
    int lane = threadIdx.x & 31, wid = threadIdx.x >> 5;
    __shared__ int warpsum[32];
    int x = v;
#pragma unroll
    for (int o = 1; o < 32; o <<= 1) {
        int y = __shfl_up_sync(0xffffffffu, x, o);
        if (lane >= o) x += y;
    }
    if (lane == 31) warpsum[wid] = x;
    __syncthreads();
    if (wid == 0) {
        int w = warpsum[lane];
#pragma unroll
        for (int o = 1; o < 32; o <<= 1) {
            int y = __shfl_up_sync(0xffffffffu, w, o);
            if (lane >= o) w += y;
        }
        warpsum[lane] = w;
    }
    __syncthreads();
    int incl = x + (wid > 0 ? warpsum[wid - 1] : 0);
    if (i < NN) rowptr[t * (NN + 1) + i + 1] = incl;
    if (threadIdx.x == 1023) bsum[t * NBLK + b] = incl;
}

// phase 2: exclusive scan of NBLK chunk totals per type (64 threads cover 49)
__global__ void scan2(int* __restrict__ bsum) {
    int t = blockIdx.x;
    int lane = threadIdx.x & 31, w = threadIdx.x >> 5;
    int v = (threadIdx.x < NBLK) ? bsum[t * NBLK + threadIdx.x] : 0;
    int x = v;
#pragma unroll
    for (int o = 1; o < 32; o <<= 1) {
        int y = __shfl_up_sync(0xffffffffu, x, o);
        if (lane >= o) x += y;
    }
    __shared__ int ws[2];
    if (lane == 31) ws[w] = x;
    __syncthreads();
    if (w == 1) x += ws[0];
    if (threadIdx.x < NBLK) bsum[t * NBLK + threadIdx.x] = x - v;
}

// phase 3: apply chunk offsets, write wofs, set rowptr[0]
__global__ void scan3(const int* __restrict__ deg, int* __restrict__ rowptr,
                      const int* __restrict__ bsum, int* __restrict__ wofs) {
    int t = blockIdx.y;
    int i = blockIdx.x * blockDim.x + threadIdx.x;
    if (i >= NN) return;
    int r = rowptr[t * (NN + 1) + i + 1] + bsum[t * NBLK + (i >> 10)];
    rowptr[t * (NN + 1) + i + 1] = r;
    wofs[t * NN + i] = r - deg[t * NN + i];
    if (i == 0) rowptr[t * (NN + 1)] = 0;
}

__global__ void csr_fill(const int* __restrict__ e0, const int* __restrict__ e1,
                         const int* __restrict__ e2, const int* __restrict__ e3,
                         int* __restrict__ wofs, int* __restrict__ csrc) {
    int g = blockIdx.x * blockDim.x + threadIdx.x;
    if (g >= 4 * EE) return;
    int t = g / EE, e = g - t * EE;
    const int* ei = t == 0 ? e0 : t == 1 ? e1 : t == 2 ? e2 : e3;
    int src = ei[e], dst = ei[EE + e];
    int pos = atomicAdd(wofs + t * NN + dst, 1);
    csrc[t * EE + pos] = src;
}

// ---------------- GEMM core: o[8][8] = A-tile @ B, duplicated-As FFMA2 ----------------
__device__ __forceinline__ void gemm_core(
    const float* __restrict__ A, const float* __restrict__ B,
    int Mrows, float o[8][8])
{
    __shared__ float As2[16][256];   // [k][2*row] duplicated pairs
    __shared__ float Bs[16][128];
    const int tid = threadIdx.x;
    const int tx = tid & 15;
    const int ty = tid >> 4;
    const int rbase = blockIdx.x * 128;

    unsigned long long acc[8][4];
#pragma unroll
    for (int i = 0; i < 8; i++)
#pragma unroll
        for (int j = 0; j < 4; j++) acc[i][j] = 0ull;

    const int arow = tid >> 1;
    const int aq   = (tid & 1) * 8;
    const int bk   = tid >> 4;
    const int bc   = (tid & 15) * 8;

    for (int k0 = 0; k0 < 128; k0 += 16) {
        float av[8];
        {
            float4 av0 = make_float4(0.f, 0.f, 0.f, 0.f), av1 = av0;
            int r = rbase + arow;
            if (r < Mrows) {
                av0 = *(const float4*)&A[(size_t)r * 128 + k0 + aq];
                av1 = *(const float4*)&A[(size_t)r * 128 + k0 + aq + 4];
            }
            av[0] = av0.x; av[1] = av0.y; av[2] = av0.z; av[3] = av0.w;
            av[4] = av1.x; av[5] = av1.y; av[6] = av1.z; av[7] = av1.w;
        }
#pragma unroll
        for (int j = 0; j < 8; j++)
            *(float2*)&As2[aq + j][2 * arow] = make_float2(av[j], av[j]);
        *(float4*)&Bs[bk][bc]     = *(const float4*)&B[(size_t)(k0 + bk) * 128 + bc];
        *(float4*)&Bs[bk][bc + 4] = *(const float4*)&B[(size_t)(k0 + bk) * 128 + bc + 4];
        __syncthreads();
#pragma unroll
        for (int k = 0; k < 16; k++) {
            unsigned long long ap[8];
            ulonglong2 a01 = *(const ulonglong2*)&As2[k][ty * 16];
            ulonglong2 a23 = *(const ulonglong2*)&As2[k][ty * 16 + 4];
            ulonglong2 a45 = *(const ulonglong2*)&As2[k][ty * 16 + 8];
            ulonglong2 a67 = *(const ulonglong2*)&As2[k][ty * 16 + 12];
            ap[0] = a01.x; ap[1] = a01.y; ap[2] = a23.x; ap[3] = a23.y;
            ap[4] = a45.x; ap[5] = a45.y; ap[6] = a67.x; ap[7] = a67.y;
            unsigned long long bp[4];
            ulonglong2 b01 = *(const ulonglong2*)&Bs[k][tx * 8];
            ulonglong2 b23 = *(const ulonglong2*)&Bs[k][tx * 8 + 4];
            bp[0] = b01.x; bp[1] = b01.y; bp[2] = b23.x; bp[3] = b23.y;
#pragma unroll
            for (int i = 0; i < 8; i++)
#pragma unroll
                for (int j = 0; j < 4; j++)
                    asm("fma.rn.f32x2 %0, %1, %2, %0;" : "+l"(acc[i][j]) : "l"(ap[i]), "l"(bp[j]));
        }
        __syncthreads();
    }
#pragma unroll
    for (int i = 0; i < 8; i++)
#pragma unroll
        for (int j = 0; j < 4; j++) {
            float lo, hi;
            asm("mov.b64 {%0, %1}, %2;" : "=f"(lo), "=f"(hi) : "l"(acc[i][j]));
            o[i][2 * j] = lo; o[i][2 * j + 1] = hi;
        }
}

// GAT GEMM + fused AL/AR epilogue. blockIdx.y = edge type.
__global__ __launch_bounds__(256) void gemm_gat(
    const float* __restrict__ A, const float* __restrict__ Wbase,
    const float* __restrict__ asrc, const float* __restrict__ adst,
    float* __restrict__ Cbase, float* __restrict__ AL, float* __restrict__ AR,
    int Mrows)
{
    int t = blockIdx.y;
    float o[8][8];
    gemm_core(A, Wbase + (size_t)t * 16384, Mrows, o);
    const int tx = threadIdx.x & 15, ty = threadIdx.x >> 4;
    const int rbase = blockIdx.x * 128;
    float* C = Cbase + (size_t)t * ND;
    float as_[8], ad_[8];
#pragma unroll
    for (int j = 0; j < 8; j++) {
        as_[j] = asrc[t * DD + tx * 8 + j];
        ad_[j] = adst[t * DD + tx * 8 + j];
    }
#pragma unroll
    for (int i = 0; i < 8; i++) {
        int r = rbase + ty * 8 + i;
        float al = 0.f, ar = 0.f;
#pragma unroll
        for (int j = 0; j < 8; j++) { al += o[i][j] * as_[j]; ar += o[i][j] * ad_[j]; }
        al += __shfl_xor_sync(0xffffffffu, al, 1);
        ar += __shfl_xor_sync(0xffffffffu, ar, 1);
        if (r < Mrows) {
            *(float4*)&C[(size_t)r * 128 + tx * 8]     = make_float4(o[i][0], o[i][1], o[i][2], o[i][3]);
            *(float4*)&C[(size_t)r * 128 + tx * 8 + 4] = make_float4(o[i][4], o[i][5], o[i][6], o[i][7]);
            if (!(tx & 1)) {
                AL[(size_t)t * NN * 8 + r * 8 + (tx >> 1)] = al;
                AR[(size_t)t * NN * 8 + r * 8 + (tx >> 1)] = ar;
            }
        }
    }
}

// up-to-3 distinct B/bias, C slices at Cbase + y*ND
__global__ __launch_bounds__(256) void gemm3(
    const float* __restrict__ A,
    const float* __restrict__ B0, const float* __restrict__ B1, const float* __restrict__ B2,
    const float* __restrict__ c0, const float* __restrict__ c1, const float* __restrict__ c2,
    float* __restrict__ Cbase, int Mrows)
{
    int y = blockIdx.y;
    const float* B = y == 0 ? B0 : y == 1 ? B1 : B2;
    const float* bias = y == 0 ? c0 : y == 1 ? c1 : c2;
    float o[8][8];
    gemm_core(A, B, Mrows, o);
    const int tx = threadIdx.x & 15, ty = threadIdx.x >> 4;
    const int rbase = blockIdx.x * 128;
    float* C = Cbase + (size_t)y * ND;
    float bb[8];
#pragma unroll
    for (int j = 0; j < 8; j++) bb[j] = bias[tx * 8 + j];
#pragma unroll
    for (int i = 0; i < 8; i++) {
        int r = rbase + ty * 8 + i;
        if (r < Mrows) {
            *(float4*)&C[(size_t)r * 128 + tx * 8] =
                make_float4(o[i][0] + bb[0], o[i][1] + bb[1], o[i][2] + bb[2], o[i][3] + bb[3]);
            *(float4*)&C[(size_t)r * 128 + tx * 8 + 4] =
                make_float4(o[i][4] + bb[4], o[i][5] + bb[5], o[i][6] + bb[6], o[i][7] + bb[7]);
        }
    }
}

// Wo GEMM + fused skip-mix + rmsnorm + residual + gelu epilogue.
__global__ __launch_bounds__(256) void gemm_wo_fin(
    const float* __restrict__ A, const float* __restrict__ B,
    const float* __restrict__ bias,
    const float* __restrict__ H, const float* __restrict__ skip,
    const float* __restrict__ g3, float* __restrict__ out, int Mrows)
{
    float o[8][8];
    gemm_core(A, B, Mrows, o);
    const int tx = threadIdx.x & 15, ty = threadIdx.x >> 4;
    const int rbase = blockIdx.x * 128;
    const unsigned hm = 0xFFFFu << (threadIdx.x & 16);
    float beta = 1.0f / (1.0f + __expf(-skip[0]));
    float bb[8], gg[8];
#pragma unroll
    for (int j = 0; j < 8; j++) {
        bb[j] = bias[tx * 8 + j];
        gg[j] = g3[tx * 8 + j];
    }
#pragma unroll
    for (int i = 0; i < 8; i++) {
        int r = rbase + ty * 8 + i;
        if (r < Mrows) {          // uniform per half-warp (r independent of tx)
            float hv[8], y[8];
            float4 h0 = *(const float4*)&H[(size_t)r * 128 + tx * 8];
            float4 h1 = *(const float4*)&H[(size_t)r * 128 + tx * 8 + 4];
            hv[0] = h0.x; hv[1] = h0.y; hv[2] = h0.z; hv[3] = h0.w;
            hv[4] = h1.x; hv[5] = h1.y; hv[6] = h1.z; hv[7] = h1.w;
            float ssq = 0.f;
#pragma unroll
            for (int j = 0; j < 8; j++) {
                y[j] = beta * (o[i][j] + bb[j]) + (1.0f - beta) * hv[j];
                ssq += y[j] * y[j];
            }
            ssq += __shfl_xor_sync(hm, ssq, 1);
            ssq += __shfl_xor_sync(hm, ssq, 2);
            ssq += __shfl_xor_sync(hm, ssq, 4);
            ssq += __shfl_xor_sync(hm, ssq, 8);
            float rr = rsqrtf(ssq * (1.0f / DD) + 1e-6f);
            float ov[8];
#pragma unroll
            for (int j = 0; j < 8; j++) ov[j] = gelu_f(hv[j] + gg[j] * y[j] * rr);
            *(float4*)&out[(size_t)r * 128 + tx * 8]     = make_float4(ov[0], ov[1], ov[2], ov[3]);
            *(float4*)&out[(size_t)r * 128 + tx * 8 + 4] = make_float4(ov[4], ov[5], ov[6], ov[7]);
        }
    }
}

// ---------------- GAT aggregation (online softmax, warp per node) ----------------
__global__ __launch_bounds__(256) void gat_agg(
    const int* __restrict__ rowptr, const int* __restrict__ csrc,
    const float* __restrict__ AL, const float* __restrict__ AR,
    const float* __restrict__ XW4,
    const float* __restrict__ b, const float* __restrict__ g,
    float* __restrict__ H)
{
    int n = (blockIdx.x * blockDim.x + threadIdx.x) >> 5;
    if (n >= NN) return;
    int lane = threadIdx.x & 31;
    int hsrc = lane >> 2;
    float4 tot = make_float4(0.f, 0.f, 0.f, 0.f);

    for (int t = 0; t < TT; t++) {
        const float* ALt = AL + (size_t)t * NN * 8;
        const float* ARt = AR + (size_t)t * NN * 8;
        const float* XWt = XW4 + (size_t)t * ND;
        int beg = rowptr[t * (NN + 1) + n];
        int end = rowptr[t * (NN + 1) + n + 1];

        float arh = ARt[n * 8 + hsrc];
        float vs = ALt[n * 8 + hsrc] + arh;
        vs = vs > 0.f ? vs : 0.2f * vs;
        float m = vs, s = 1.0f;
        float4 acc = *(const float4*)&XWt[(size_t)n * DD + lane * 4];

        for (int p = beg; p < end; p++) {
            int src = csrc[t * EE + p];
            float v = ALt[src * 8 + hsrc] + arh;
            v = v > 0.f ? v : 0.2f * v;
            float mn = fmaxf(m, v);
            float sc = __expf(m - mn);
            float pw = __expf(v - mn);
            s = s * sc + pw;
            m = mn;
            float4 xv = *(const float4*)&XWt[(size_t)src * DD + lane * 4];
            acc.x = acc.x * sc + xv.x * pw;
            acc.y = acc.y * sc + xv.y * pw;
            acc.z = acc.z * sc + xv.z * pw;
            acc.w = acc.w * sc + xv.w * pw;
        }
        float inv = 1.0f / s;
        tot.x += acc.x * inv; tot.y += acc.y * inv;
        tot.z += acc.z * inv; tot.w += acc.w * inv;
    }

    int c = lane * 4;
#pragma unroll
    for (int t = 0; t < TT; t++) {
        float4 bb = *(const float4*)&b[t * DD + c];
        tot.x += bb.x; tot.y += bb.y; tot.z += bb.z; tot.w += bb.w;
    }
    float ss = tot.x * tot.x + tot.y * tot.y + tot.z * tot.z + tot.w * tot.w;
#pragma unroll
    for (int o = 16; o; o >>= 1) ss += __shfl_xor_sync(0xffffffffu, ss, o);
    float r = rsqrtf(ss * (1.0f / DD) + 1e-6f);
    float4 gg = *(const float4*)&g[c];
    float4 hv = *(const float4*)&H[(size_t)n * DD + c];
    float4 ov;
    ov.x = gelu_f(hv.x + gg.x * tot.x * r);
    ov.y = gelu_f(hv.y + gg.y * tot.y * r);
    ov.z = gelu_f(hv.z + gg.z * tot.z * r);
    ov.w = gelu_f(hv.w + gg.w * tot.w * r);
    *(float4*)&H[(size_t)n * DD + c] = ov;
}

// ---------------- HGT ----------------
// 4 outputs/thread: KA[t][n,h*16+f0..f0+3]
__global__ void hgt_rel4(const float* __restrict__ K, const float* __restrict__ V,
                         const float* __restrict__ arel, const float* __restrict__ mrel,
                         float* __restrict__ KA, float* __restrict__ VM)
{
    int t = blockIdx.y, isV = blockIdx.z;
    const float* X = isV ? V : K;
    const float* R = (isV ? mrel : arel) + t * 2048;
    float* Y = (isV ? VM : KA) + (size_t)t * ND;
    int g = blockIdx.x * blockDim.x + threadIdx.x;
    if (g >= ND / 4) return;
    int n = g >> 5, c4 = g & 31, h = c4 >> 2, f0 = (c4 & 3) * 4;
    const float* xp = X + (size_t)n * DD + h * 16;
    const float* rp = R + h * 256 + f0;
    float xv[16];
#pragma unroll
    for (int q = 0; q < 4; q++) *(float4*)&xv[q * 4] = *(const float4*)&xp[q * 4];
    unsigned long long a0 = 0ull, a1 = 0ull;
#pragma unroll
    for (int d = 0; d < 16; d++) {
        unsigned long long xb;
        asm("mov.b64 %0, {%1, %1};" : "=l"(xb) : "f"(xv[d]));
        ulonglong2 rb = *(const ulonglong2*)&rp[d * 16];
        asm("fma.rn.f32x2 %0, %1, %2, %0;" : "+l"(a0) : "l"(xb), "l"(rb.x));
        asm("fma.rn.f32x2 %0, %1, %2, %0;" : "+l"(a1) : "l"(xb), "l"(rb.y));
    }
    ulonglong2 st; st.x = a0; st.y = a1;
    *(ulonglong2*)&Y[(size_t)n * DD + h * 16 + f0] = st;
}

// Fused HGT attention + aggregation (joint online softmax), warp per node.
__global__ __launch_bounds__(256) void hgt_fused(
    const int* __restrict__ rowptr, const int* __restrict__ csrc,
    const float* __restrict__ Q, const float* __restrict__ KA4,
    const float* __restrict__ VM4, const float* __restrict__ prel,
    float* __restrict__ TMP)
{
    int n = (blockIdx.x * blockDim.x + threadIdx.x) >> 5;
    if (n >= NN) return;
    int lane = threadIdx.x & 31;
    int hsrc = lane >> 2;

    float4 qv = *(const float4*)&Q[(size_t)n * DD + lane * 4];
    float m = -1e30f, s = 0.f;
    float4 acc = make_float4(0.f, 0.f, 0.f, 0.f);

    for (int t = 0; t < TT; t++) {
        const float* KAt = KA4 + (size_t)t * ND;
        const float* VMt = VM4 + (size_t)t * ND;
        float pr = prel[t * 8 + hsrc] * 0.25f;
        int beg = rowptr[t * (NN + 1) + n];
        int end = rowptr[t * (NN + 1) + n + 1];
        for (int p = beg; p < end; p++) {
            int src = csrc[t * EE + p];
            float4 ka = *(const float4*)&KAt[(size_t)src * DD + lane * 4];
            float d = qv.x * ka.x + qv.y * ka.y + qv.z * ka.z + qv.w * ka.w;
            d += __shfl_xor_sync(0xffffffffu, d, 1);
            d += __shfl_xor_sync(0xffffffffu, d, 2);
            float l = d * pr;
            float mn = fmaxf(m, l);
            float sc = __expf(m - mn);
            float pw = __expf(l - mn);
            s = s * sc + pw;
            m = mn;
            float4 vm = *(const float4*)&VMt[(size_t)src * DD + lane * 4];
            acc.x = acc.x * sc + vm.x * pw;
            acc.y = acc.y * sc + vm.y * pw;
            acc.z = acc.z * sc + vm.z * pw;
            acc.w = acc.w * sc + vm.w * pw;
        }
    }
    float inv = (s > 0.f) ? 1.0f / s : 0.f;
    int c = lane * 4;
    float4 ov;
    ov.x = gelu_f(acc.x * inv);
    ov.y = gelu_f(acc.y * inv);
    ov.z = gelu_f(acc.z * inv);
    ov.w = gelu_f(acc.w * inv);
    *(float4*)&TMP[(size_t)n * DD + c] = ov;
}

// ---------------- driver ----------------
extern "C" void kernel_launch(void* const* d_in, const int* in_sizes, int n_in,
                              void* d_out, int out_size)
{
    const float* zL  = (const float*)d_in[0];
    const float* zH  = (const float*)d_in[1];
    const float* xe  = (const float*)d_in[2];
    const float* W1  = (const float*)d_in[3];
    const float* as1 = (const float*)d_in[4];
    const float* ad1 = (const float*)d_in[5];
    const float* b1  = (const float*)d_in[6];
    const float* W2  = (const float*)d_in[7];
    const float* as2 = (const float*)d_in[8];
    const float* ad2 = (const float*)d_in[9];
    const float* b2  = (const float*)d_in[10];
    const float* Wk  = (const float*)d_in[11];
    const float* bk  = (const float*)d_in[12];
    const float* Wq  = (const float*)d_in[13];
    const float* bq  = (const float*)d_in[14];
    const float* Wv  = (const float*)d_in[15];
    const float* bv  = (const float*)d_in[16];
    const float* arel= (const float*)d_in[17];
    const float* mrel= (const float*)d_in[18];
    const float* prel= (const float*)d_in[19];
    const float* Wo  = (const float*)d_in[20];
    const float* bo  = (const float*)d_in[21];
    const float* skip= (const float*)d_in[22];
    const float* g1  = (const float*)d_in[23];
    const float* g2  = (const float*)d_in[24];
    const float* g3  = (const float*)d_in[25];
    const int* e0 = (const int*)d_in[26];
    const int* e1 = (const int*)d_in[27];
    const int* e2 = (const int*)d_in[28];
    const int* e3 = (const int*)d_in[29];

    float* SB = nullptr;
    cudaGetSymbolAddress((void**)&SB, d_scratch);
    float* H    = SB;
    float* Q    = SB + (size_t)ND;       // Q,K,V contiguous
    float* K    = SB + 2 * (size_t)ND;
    float* V    = SB + 3 * (size_t)ND;
    float* TMP  = SB + 4 * (size_t)ND;
    float* XW4  = SB + 5 * (size_t)ND;   // 4 slices; reused as KA4
    float* VM4  = SB + 9 * (size_t)ND;   // 4 slices
    float* AL   = SB + 13 * (size_t)ND;
    float* AR   = AL + 4 * (size_t)NN * 8;
    int*   IB   = (int*)(AR + 4 * (size_t)NN * 8);
    int* deg    = IB;
    int* rowptr = IB + 4 * NN;
    int* wofs   = rowptr + 4 * (NN + 1);
    int* csrc   = wofs + 4 * NN;
    int* bsum   = csrc + 4 * EE;

    const int TPB  = 256;
    const int gND  = (ND + TPB - 1) / TPB;
    const int g4E  = (4 * EE + TPB - 1) / TPB;
    const int g4N  = (4 * NN + TPB - 1) / TPB;
    const int gGEMM = (NN + 127) / 128;
    const int gWARP = (NN * 32 + TPB - 1) / TPB;

    add3_k<<<gND, TPB>>>(zL, zH, xe, H);                       // 1
    fill0_k<<<g4N, TPB>>>(deg, 4 * NN);                        // 2
    deg_count<<<g4E, TPB>>>(e0, e1, e2, e3, deg);              // 3
    {
        dim3 gg(gGEMM, 4);                                     // 4 (profiled)
        gemm_gat<<<gg, 256>>>(H, W1, as1, ad1, XW4, AL, AR, NN);
    }
    { dim3 gs(NBLK, 4); scan1<<<gs, 1024>>>(deg, rowptr, bsum); }          // 5
    scan2<<<4, 64>>>(bsum);                                                 // 6
    { dim3 gs((NN + TPB - 1) / TPB, 4); scan3<<<gs, TPB>>>(deg, rowptr, bsum, wofs); } // 7
    csr_fill<<<g4E, TPB>>>(e0, e1, e2, e3, wofs, csrc);                     // 8

    gat_agg<<<gWARP, TPB>>>(rowptr, csrc, AL, AR, XW4, b1, g1, H);          // 9
    {
        dim3 gg(gGEMM, 4);
        gemm_gat<<<gg, 256>>>(H, W2, as2, ad2, XW4, AL, AR, NN);            // 10
    }
    gat_agg<<<gWARP, TPB>>>(rowptr, csrc, AL, AR, XW4, b2, g2, H);          // 11

    // HGT
    {
        dim3 gg(gGEMM, 3);
        gemm3<<<gg, 256>>>(H, Wq, Wk, Wv, bq, bk, bv, Q, NN);               // 12
    }
    {
        dim3 gr((ND / 4 + TPB - 1) / TPB, 4, 2);
        hgt_rel4<<<gr, TPB>>>(K, V, arel, mrel, XW4 /*KA4*/, VM4);          // 13
    }
    hgt_fused<<<gWARP, TPB>>>(rowptr, csrc, Q, XW4, VM4, prel, TMP);        // 14
    gemm_wo_fin<<<gGEMM, 256>>>(TMP, Wo, bo, H, skip, g3, (float*)d_out, NN); // 15
}